// round 4
// baseline (speedup 1.0000x reference)
#include <cuda_runtime.h>
#include <cstdint>

#define BATCH 2
#define SEQ   4096
#define DMODEL 512
#define NHEAD 8
#define HDIM  64
#define FULLM 0xffffffffu

// Scratch (allocation-free rule: __device__ globals)
__device__ float g_q[BATCH * NHEAD * SEQ * HDIM];
__device__ float g_k[BATCH * NHEAD * SEQ * HDIM];
__device__ float g_v[BATCH * NHEAD * SEQ * HDIM];
__device__ float g_attn[BATCH * SEQ * DMODEL];

__device__ __forceinline__ unsigned f2tf(float f) {
    unsigned u;
    asm("cvt.rna.tf32.f32 %0, %1;" : "=r"(u) : "f"(f));
    return u;
}

__device__ __forceinline__ float ex2(float x) {
    float r;
    asm("ex2.approx.f32 %0, %1;" : "=f"(r) : "f"(x));
    return r;
}

__device__ __forceinline__ void mma_tf32(
    float& d0, float& d1, float& d2, float& d3,
    unsigned a0, unsigned a1, unsigned a2, unsigned a3,
    unsigned b0, unsigned b1)
{
    asm volatile(
        "mma.sync.aligned.m16n8k8.row.col.f32.tf32.tf32.f32 "
        "{%0,%1,%2,%3}, {%4,%5,%6,%7}, {%8,%9}, {%0,%1,%2,%3};"
        : "+f"(d0), "+f"(d1), "+f"(d2), "+f"(d3)
        : "r"(a0), "r"(a1), "r"(a2), "r"(a3), "r"(b0), "r"(b1));
}

// ---------------------------------------------------------------------------
// tf32 NT GEMM (unchanged from R3): C[m,e] = sum_k A[m,k]*W[e,k] (+bias)
// ---------------------------------------------------------------------------
__global__ __launch_bounds__(256, 2)
void gemm_tf32_kernel(const float* __restrict__ A, const float* __restrict__ W,
                      const float* __restrict__ bias, float* __restrict__ C,
                      int mode)
{
    __shared__ float As[128][36];
    __shared__ float Bs[64][36];

    const int bm = blockIdx.x * 128;
    const int bn = blockIdx.y * 64;
    const int tid = threadIdx.x;
    const int lane = tid & 31;
    const int warp = tid >> 5;
    const int gr = lane >> 2;
    const int gc = lane & 3;
    const int wm = (warp >> 1) * 32;
    const int wn = (warp & 1) * 32;

    float c[2][4][4] = {};

    for (int k0 = 0; k0 < 512; k0 += 32) {
        #pragma unroll
        for (int i = 0; i < 4; i++) {
            int idx = tid + i * 256;
            int r = idx >> 3, c4 = (idx & 7) * 4;
            float4 v = *(const float4*)(A + (size_t)(bm + r) * 512 + k0 + c4);
            float4 o;
            o.x = __uint_as_float(f2tf(v.x)); o.y = __uint_as_float(f2tf(v.y));
            o.z = __uint_as_float(f2tf(v.z)); o.w = __uint_as_float(f2tf(v.w));
            *(float4*)&As[r][c4] = o;
        }
        #pragma unroll
        for (int i = 0; i < 2; i++) {
            int idx = tid + i * 256;
            int r = idx >> 3, c4 = (idx & 7) * 4;
            float4 v = *(const float4*)(W + (size_t)(bn + r) * 512 + k0 + c4);
            float4 o;
            o.x = __uint_as_float(f2tf(v.x)); o.y = __uint_as_float(f2tf(v.y));
            o.z = __uint_as_float(f2tf(v.z)); o.w = __uint_as_float(f2tf(v.w));
            *(float4*)&Bs[r][c4] = o;
        }
        __syncthreads();

        #pragma unroll
        for (int kk = 0; kk < 4; kk++) {
            const int kc = kk * 8 + gc;
            unsigned a[2][4], b[4][2];
            #pragma unroll
            for (int mt = 0; mt < 2; mt++) {
                int r = wm + mt * 16 + gr;
                a[mt][0] = __float_as_uint(As[r][kc]);
                a[mt][1] = __float_as_uint(As[r + 8][kc]);
                a[mt][2] = __float_as_uint(As[r][kc + 4]);
                a[mt][3] = __float_as_uint(As[r + 8][kc + 4]);
            }
            #pragma unroll
            for (int nt = 0; nt < 4; nt++) {
                int r = wn + nt * 8 + gr;
                b[nt][0] = __float_as_uint(Bs[r][kc]);
                b[nt][1] = __float_as_uint(Bs[r][kc + 4]);
            }
            #pragma unroll
            for (int mt = 0; mt < 2; mt++)
                #pragma unroll
                for (int nt = 0; nt < 4; nt++)
                    mma_tf32(c[mt][nt][0], c[mt][nt][1], c[mt][nt][2], c[mt][nt][3],
                             a[mt][0], a[mt][1], a[mt][2], a[mt][3],
                             b[nt][0], b[nt][1]);
        }
        __syncthreads();
    }

    #pragma unroll
    for (int mt = 0; mt < 2; mt++) {
        #pragma unroll
        for (int nt = 0; nt < 4; nt++) {
            const int r0 = bm + wm + mt * 16 + gr;
            const int e0 = bn + wn + nt * 8 + 2 * gc;
            float v0 = c[mt][nt][0], v1 = c[mt][nt][1];
            float v2 = c[mt][nt][2], v3 = c[mt][nt][3];
            if (mode == 0) {
                const float b0 = bias[e0], b1 = bias[e0 + 1];
                *(float2*)&C[(size_t)r0 * 512 + e0]        = make_float2(v0 + b0, v1 + b1);
                *(float2*)&C[(size_t)(r0 + 8) * 512 + e0]  = make_float2(v2 + b0, v3 + b1);
            } else {
                const int hh = e0 >> 6, dd = e0 & 63;
                const int bb0 = r0 / SEQ, ss0 = r0 % SEQ;
                const int bb1 = (r0 + 8) / SEQ, ss1 = (r0 + 8) % SEQ;
                *(float2*)&C[(((size_t)bb0 * NHEAD + hh) * SEQ + ss0) * HDIM + dd] =
                    make_float2(v0, v1);
                *(float2*)&C[(((size_t)bb1 * NHEAD + hh) * SEQ + ss1) * HDIM + dd] =
                    make_float2(v2, v3);
            }
        }
    }
}

// ---------------------------------------------------------------------------
// Flash attention, tf32 MMA, fragment-packed smem (LDS.128 B-frags).
// Block = 128 threads (4 warps x 16 q-rows = 64 q-rows). 64-key tiles.
// Kf layout: row k (0..63), packed col c' = (d>>4)*16 + (d&3)*4 + ((d>>3)&1)*2
//            + ((d>>2)&1), stride 80.  float4 at [k*80 + kcp*16 + gc*4] gives
//            {b0(kc=2kcp), b1(2kcp), b0(2kcp+1), b1(2kcp+1)} for QK^T.
// Vf layout: col d (0..63), packed row with same mapping on k, plus rotation
//            swizzle rot(d) = ((d>>2)&7)*4 (mod 64) for staging-bank spread.
// ---------------------------------------------------------------------------
__global__ __launch_bounds__(128, 3)
void attn_tc_kernel(const float* __restrict__ Q, const float* __restrict__ Km,
                    const float* __restrict__ V, float* __restrict__ O)
{
    __shared__ float Kf[64 * 80];
    __shared__ float Vf[64 * 80];

    const int bh = blockIdx.y;
    const int NT = SEQ / 64;                     // 64 q-tiles
    const int xt = blockIdx.x;
    const int qtile = (xt & 1) ? (NT - 1 - (xt >> 1)) : (xt >> 1);
    const int qb = qtile * 64;

    const int tid = threadIdx.x;
    const int lane = tid & 31;
    const int warp = tid >> 5;
    const int gr = lane >> 2;
    const int gc = lane & 3;
    const int grh = gr >> 2;
    const int qrow0 = qb + warp * 16 + gr;       // rows qrow0, qrow0+8

    const float* Qb = Q  + (size_t)bh * SEQ * HDIM;
    const float* Kb = Km + (size_t)bh * SEQ * HDIM;
    const float* Vb = V  + (size_t)bh * SEQ * HDIM;

    // Q fragments, pre-scaled by 0.125 * log2(e)  (softmax in base-2 domain)
    const float qs = 0.125f * 1.4426950408889634f;
    unsigned qf[8][4];
    #pragma unroll
    for (int kc = 0; kc < 8; kc++) {
        qf[kc][0] = f2tf(Qb[(size_t)qrow0 * 64 + kc * 8 + gc] * qs);
        qf[kc][1] = f2tf(Qb[(size_t)(qrow0 + 8) * 64 + kc * 8 + gc] * qs);
        qf[kc][2] = f2tf(Qb[(size_t)qrow0 * 64 + kc * 8 + gc + 4] * qs);
        qf[kc][3] = f2tf(Qb[(size_t)(qrow0 + 8) * 64 + kc * 8 + gc + 4] * qs);
    }

    float o[8][4];
    #pragma unroll
    for (int dt = 0; dt < 8; dt++)
        #pragma unroll
        for (int j = 0; j < 4; j++) o[dt][j] = 0.f;
    float m0 = -1e30f, m1 = -1e30f, l0 = 0.f, l1 = 0.f;

    const int ntiles = qb / 64 + 1;

    for (int kt = 0; kt < ntiles; kt++) {
        // ---- stage K and V tiles into fragment-packed layouts ----
        #pragma unroll
        for (int i = 0; i < 8; i++) {
            const int idx = tid + i * 128;
            const int r = idx >> 4;
            const int c4 = (idx & 15) * 4;
            float4 kv = *(const float4*)(Kb + (size_t)(kt * 64 + r) * 64 + c4);
            float4 vv = *(const float4*)(Vb + (size_t)(kt * 64 + r) * 64 + c4);
            // K: row r, packed col c'(d)
            const float kvv[4] = {kv.x, kv.y, kv.z, kv.w};
            const float vvv[4] = {vv.x, vv.y, vv.z, vv.w};
            // V packed-row of k=r (swizzle base depends on d)
            const int vrb  = ((r >> 4) << 4) + ((r & 3) << 2);
            const int voff = (((r >> 3) & 1) << 1) + ((r >> 2) & 1);
            #pragma unroll
            for (int e = 0; e < 4; e++) {
                const int d = c4 + e;
                const int cp = ((d >> 4) << 4) + ((d & 3) << 2)
                             + (((d >> 3) & 1) << 1) + ((d >> 2) & 1);
                Kf[r * 80 + cp] = __uint_as_float(f2tf(kvv[e]));
                const int rot = (((d >> 2) & 7) << 2);
                const int sr = ((vrb + rot) & 63) + voff;
                Vf[d * 80 + sr] = __uint_as_float(f2tf(vvv[e]));
            }
        }
        __syncthreads();

        // ---- S = Q K^T ----
        float s[8][4];
        #pragma unroll
        for (int nt = 0; nt < 8; nt++)
            #pragma unroll
            for (int j = 0; j < 4; j++) s[nt][j] = 0.f;

        #pragma unroll
        for (int kcp = 0; kcp < 4; kcp++) {
            #pragma unroll
            for (int nt = 0; nt < 8; nt++) {
                float4 kb = *(const float4*)&Kf[(nt * 8 + gr) * 80 + kcp * 16 + gc * 4];
                mma_tf32(s[nt][0], s[nt][1], s[nt][2], s[nt][3],
                         qf[2 * kcp][0], qf[2 * kcp][1], qf[2 * kcp][2], qf[2 * kcp][3],
                         __float_as_uint(kb.x), __float_as_uint(kb.y));
                mma_tf32(s[nt][0], s[nt][1], s[nt][2], s[nt][3],
                         qf[2 * kcp + 1][0], qf[2 * kcp + 1][1],
                         qf[2 * kcp + 1][2], qf[2 * kcp + 1][3],
                         __float_as_uint(kb.z), __float_as_uint(kb.w));
            }
        }

        // ---- causal mask (only the last key tile crosses the diagonal) ----
        if (kt == ntiles - 1) {
            #pragma unroll
            for (int nt = 0; nt < 8; nt++) {
                const int col = kt * 64 + nt * 8 + 2 * gc;
                if (col > qrow0)          s[nt][0] = -1e30f;
                if (col + 1 > qrow0)      s[nt][1] = -1e30f;
                if (col > qrow0 + 8)      s[nt][2] = -1e30f;
                if (col + 1 > qrow0 + 8)  s[nt][3] = -1e30f;
            }
        }

        // ---- online softmax (base-2 domain) ----
        float tm0 = -1e30f, tm1 = -1e30f;
        #pragma unroll
        for (int nt = 0; nt < 8; nt++) {
            tm0 = fmaxf(tm0, fmaxf(s[nt][0], s[nt][1]));
            tm1 = fmaxf(tm1, fmaxf(s[nt][2], s[nt][3]));
        }
        tm0 = fmaxf(tm0, __shfl_xor_sync(FULLM, tm0, 1, 4));
        tm0 = fmaxf(tm0, __shfl_xor_sync(FULLM, tm0, 2, 4));
        tm1 = fmaxf(tm1, __shfl_xor_sync(FULLM, tm1, 1, 4));
        tm1 = fmaxf(tm1, __shfl_xor_sync(FULLM, tm1, 2, 4));

        const float nm0 = fmaxf(m0, tm0);
        const float nm1 = fmaxf(m1, tm1);
        const float sc0 = ex2(m0 - nm0);
        const float sc1 = ex2(m1 - nm1);

        float r0 = 0.f, r1 = 0.f;
        #pragma unroll
        for (int nt = 0; nt < 8; nt++) {
            s[nt][0] = ex2(s[nt][0] - nm0);
            s[nt][1] = ex2(s[nt][1] - nm0);
            s[nt][2] = ex2(s[nt][2] - nm1);
            s[nt][3] = ex2(s[nt][3] - nm1);
            r0 += s[nt][0] + s[nt][1];
            r1 += s[nt][2] + s[nt][3];
        }
        r0 += __shfl_xor_sync(FULLM, r0, 1, 4);
        r0 += __shfl_xor_sync(FULLM, r0, 2, 4);
        r1 += __shfl_xor_sync(FULLM, r1, 1, 4);
        r1 += __shfl_xor_sync(FULLM, r1, 2, 4);
        l0 = l0 * sc0 + r0;
        l1 = l1 * sc1 + r1;

        #pragma unroll
        for (int dt = 0; dt < 8; dt++) {
            o[dt][0] *= sc0; o[dt][1] *= sc0;
            o[dt][2] *= sc1; o[dt][3] *= sc1;
        }

        // ---- O += P V ----
        const int srcA = gc >> 1;
        const int srcB = srcA + 2;
        const bool odd = (gc & 1);
        #pragma unroll
        for (int kcp = 0; kcp < 4; kcp++) {
            unsigned af[2][4];
            #pragma unroll
            for (int j = 0; j < 2; j++) {
                const int kc = 2 * kcp + j;
                float t0 = __shfl_sync(FULLM, s[kc][0], srcA, 4);
                float t1 = __shfl_sync(FULLM, s[kc][1], srcA, 4);
                float t2 = __shfl_sync(FULLM, s[kc][2], srcA, 4);
                float t3 = __shfl_sync(FULLM, s[kc][3], srcA, 4);
                float u0 = __shfl_sync(FULLM, s[kc][0], srcB, 4);
                float u1 = __shfl_sync(FULLM, s[kc][1], srcB, 4);
                float u2 = __shfl_sync(FULLM, s[kc][2], srcB, 4);
                float u3 = __shfl_sync(FULLM, s[kc][3], srcB, 4);
                af[j][0] = f2tf(odd ? t1 : t0);
                af[j][1] = f2tf(odd ? t3 : t2);
                af[j][2] = f2tf(odd ? u1 : u0);
                af[j][3] = f2tf(odd ? u3 : u2);
            }
            #pragma unroll
            for (int dt = 0; dt < 8; dt++) {
                const int d = dt * 8 + gr;
                const int sb = (kcp * 16 + gc * 4 + (((dt * 2 + grh) & 7) << 2)) & 63;
                float4 vb = *(const float4*)&Vf[d * 80 + sb];
                mma_tf32(o[dt][0], o[dt][1], o[dt][2], o[dt][3],
                         af[0][0], af[0][1], af[0][2], af[0][3],
                         __float_as_uint(vb.x), __float_as_uint(vb.y));
                mma_tf32(o[dt][0], o[dt][1], o[dt][2], o[dt][3],
                         af[1][0], af[1][1], af[1][2], af[1][3],
                         __float_as_uint(vb.z), __float_as_uint(vb.w));
            }
        }

        m0 = nm0; m1 = nm1;
        __syncthreads();
    }

    // ---- epilogue: normalize, store to [B, S, H, DH] ----
    const float inv0 = 1.f / l0;
    const float inv1 = 1.f / l1;
    const int b = bh >> 3, h = bh & 7;
    #pragma unroll
    for (int dt = 0; dt < 8; dt++) {
        const int col = dt * 8 + 2 * gc;
        *(float2*)&O[(((size_t)b * SEQ + qrow0) * NHEAD + h) * HDIM + col] =
            make_float2(o[dt][0] * inv0, o[dt][1] * inv0);
        *(float2*)&O[(((size_t)b * SEQ + qrow0 + 8) * NHEAD + h) * HDIM + col] =
            make_float2(o[dt][2] * inv1, o[dt][3] * inv1);
    }
}

// ---------------------------------------------------------------------------
extern "C" void kernel_launch(void* const* d_in, const int* in_sizes, int n_in,
                              void* d_out, int out_size)
{
    const float* x  = (const float*)d_in[0];
    const float* Wq = (const float*)d_in[1];
    const float* Wk = (const float*)d_in[2];
    const float* Wv = (const float*)d_in[3];
    const float* Wp = (const float*)d_in[4];
    const float* bp = (const float*)d_in[5];
    float* out = (float*)d_out;

    float *qp, *kp, *vp, *ap;
    cudaGetSymbolAddress((void**)&qp, g_q);
    cudaGetSymbolAddress((void**)&kp, g_k);
    cudaGetSymbolAddress((void**)&vp, g_v);
    cudaGetSymbolAddress((void**)&ap, g_attn);

    dim3 gg(BATCH * SEQ / 128, DMODEL / 64);   // (64, 8)
    gemm_tf32_kernel<<<gg, 256>>>(x, Wq, nullptr, qp, 1);
    gemm_tf32_kernel<<<gg, 256>>>(x, Wk, nullptr, kp, 1);
    gemm_tf32_kernel<<<gg, 256>>>(x, Wv, nullptr, vp, 1);

    dim3 ga(SEQ / 64, BATCH * NHEAD);           // (64, 16)
    attn_tc_kernel<<<ga, 128>>>(qp, kp, vp, ap);

    gemm_tf32_kernel<<<gg, 256>>>(ap, Wp, bp, out, 0);
}

// round 5
// speedup vs baseline: 1.1284x; 1.1284x over previous
#include <cuda_runtime.h>
#include <cstdint>

#define BATCH 2
#define SEQ   4096
#define DMODEL 512
#define NHEAD 8
#define HDIM  64
#define FULLM 0xffffffffu

// Scratch (allocation-free rule: __device__ globals)
__device__ float g_q[BATCH * NHEAD * SEQ * HDIM];   // [bh][s][d]  tf32, pre-scaled
__device__ float g_k[BATCH * NHEAD * SEQ * HDIM];   // [bh][s][cp(d)]  tf32
__device__ float g_v[BATCH * NHEAD * SEQ * HDIM];   // [bh][d][(s/64)*64+cp(s%64)] tf32
__device__ float g_attn[BATCH * SEQ * DMODEL];

__device__ __forceinline__ unsigned f2tf(float f) {
    unsigned u;
    asm("cvt.rna.tf32.f32 %0, %1;" : "=r"(u) : "f"(f));
    return u;
}

__device__ __forceinline__ float ex2(float x) {
    float r;
    asm("ex2.approx.f32 %0, %1;" : "=f"(r) : "f"(x));
    return r;
}

// fragment permutation within a 64-chunk:
// cp = (i>>4)*16 + (i&3)*4 + ((i>>3)&1)*2 + ((i>>2)&1)
__device__ __forceinline__ int cpd(int i) {
    return ((i >> 4) << 4) + ((i & 3) << 2) + (((i >> 3) & 1) << 1) + ((i >> 2) & 1);
}

__device__ __forceinline__ void mma_tf32(
    float& d0, float& d1, float& d2, float& d3,
    unsigned a0, unsigned a1, unsigned a2, unsigned a3,
    unsigned b0, unsigned b1)
{
    asm volatile(
        "mma.sync.aligned.m16n8k8.row.col.f32.tf32.tf32.f32 "
        "{%0,%1,%2,%3}, {%4,%5,%6,%7}, {%8,%9}, {%0,%1,%2,%3};"
        : "+f"(d0), "+f"(d1), "+f"(d2), "+f"(d3)
        : "r"(a0), "r"(a1), "r"(a2), "r"(a3), "r"(b0), "r"(b1));
}

// ---------------------------------------------------------------------------
// tf32 NT GEMM: C[m,e] = sum_k A[m,k]*W[e,k].
// mode 0: C row-major [M,512] + bias
// mode 1: Q scatter  [bh][s][d], value = tf32(v * 0.125*log2e)
// mode 2: K scatter  [bh][s][cp(d)], value = tf32(v)
// mode 3: V scatter  [bh][d][(s/64)*64 + cp(s%64)], value = tf32(v)
// ---------------------------------------------------------------------------
__global__ __launch_bounds__(256, 2)
void gemm_tf32_kernel(const float* __restrict__ A, const float* __restrict__ W,
                      const float* __restrict__ bias, float* __restrict__ C,
                      int mode)
{
    __shared__ float As[128][36];
    __shared__ float Bs[64][36];

    const int bm = blockIdx.x * 128;
    const int bn = blockIdx.y * 64;
    const int tid = threadIdx.x;
    const int lane = tid & 31;
    const int warp = tid >> 5;
    const int gr = lane >> 2;
    const int gc = lane & 3;
    const int wm = (warp >> 1) * 32;
    const int wn = (warp & 1) * 32;

    float c[2][4][4] = {};

    for (int k0 = 0; k0 < 512; k0 += 32) {
        #pragma unroll
        for (int i = 0; i < 4; i++) {
            int idx = tid + i * 256;
            int r = idx >> 3, c4 = (idx & 7) * 4;
            float4 v = *(const float4*)(A + (size_t)(bm + r) * 512 + k0 + c4);
            float4 o;
            o.x = __uint_as_float(f2tf(v.x)); o.y = __uint_as_float(f2tf(v.y));
            o.z = __uint_as_float(f2tf(v.z)); o.w = __uint_as_float(f2tf(v.w));
            *(float4*)&As[r][c4] = o;
        }
        #pragma unroll
        for (int i = 0; i < 2; i++) {
            int idx = tid + i * 256;
            int r = idx >> 3, c4 = (idx & 7) * 4;
            float4 v = *(const float4*)(W + (size_t)(bn + r) * 512 + k0 + c4);
            float4 o;
            o.x = __uint_as_float(f2tf(v.x)); o.y = __uint_as_float(f2tf(v.y));
            o.z = __uint_as_float(f2tf(v.z)); o.w = __uint_as_float(f2tf(v.w));
            *(float4*)&Bs[r][c4] = o;
        }
        __syncthreads();

        #pragma unroll
        for (int kk = 0; kk < 4; kk++) {
            const int kc = kk * 8 + gc;
            unsigned a[2][4], b[4][2];
            #pragma unroll
            for (int mt = 0; mt < 2; mt++) {
                int r = wm + mt * 16 + gr;
                a[mt][0] = __float_as_uint(As[r][kc]);
                a[mt][1] = __float_as_uint(As[r + 8][kc]);
                a[mt][2] = __float_as_uint(As[r][kc + 4]);
                a[mt][3] = __float_as_uint(As[r + 8][kc + 4]);
            }
            #pragma unroll
            for (int nt = 0; nt < 4; nt++) {
                int r = wn + nt * 8 + gr;
                b[nt][0] = __float_as_uint(Bs[r][kc]);
                b[nt][1] = __float_as_uint(Bs[r][kc + 4]);
            }
            #pragma unroll
            for (int mt = 0; mt < 2; mt++)
                #pragma unroll
                for (int nt = 0; nt < 4; nt++)
                    mma_tf32(c[mt][nt][0], c[mt][nt][1], c[mt][nt][2], c[mt][nt][3],
                             a[mt][0], a[mt][1], a[mt][2], a[mt][3],
                             b[nt][0], b[nt][1]);
        }
        __syncthreads();
    }

    const float qs = 0.125f * 1.4426950408889634f;

    #pragma unroll
    for (int mt = 0; mt < 2; mt++) {
        #pragma unroll
        for (int nt = 0; nt < 4; nt++) {
            const int r0 = bm + wm + mt * 16 + gr;
            const int e0 = bn + wn + nt * 8 + 2 * gc;
            float v0 = c[mt][nt][0], v1 = c[mt][nt][1];
            float v2 = c[mt][nt][2], v3 = c[mt][nt][3];
            if (mode == 0) {
                const float b0 = bias[e0], b1 = bias[e0 + 1];
                *(float2*)&C[(size_t)r0 * 512 + e0]       = make_float2(v0 + b0, v1 + b1);
                *(float2*)&C[(size_t)(r0 + 8) * 512 + e0] = make_float2(v2 + b0, v3 + b1);
            } else {
                const int hh = e0 >> 6, dd = e0 & 63;
                const int bh0 = (r0 / SEQ) * NHEAD + hh;
                const int ss0 = r0 % SEQ;
                const int bh1 = ((r0 + 8) / SEQ) * NHEAD + hh;
                const int ss1 = (r0 + 8) % SEQ;
                if (mode == 1) {        // Q: normal layout, scaled + rounded
                    *(float2*)&C[((size_t)bh0 * SEQ + ss0) * 64 + dd] =
                        make_float2(__uint_as_float(f2tf(v0 * qs)),
                                    __uint_as_float(f2tf(v1 * qs)));
                    *(float2*)&C[((size_t)bh1 * SEQ + ss1) * 64 + dd] =
                        make_float2(__uint_as_float(f2tf(v2 * qs)),
                                    __uint_as_float(f2tf(v3 * qs)));
                } else if (mode == 2) { // K: d-permuted rows, rounded
                    const int p0 = cpd(dd), p1 = cpd(dd + 1);
                    float* r0p = &C[((size_t)bh0 * SEQ + ss0) * 64];
                    float* r1p = &C[((size_t)bh1 * SEQ + ss1) * 64];
                    r0p[p0] = __uint_as_float(f2tf(v0));
                    r0p[p1] = __uint_as_float(f2tf(v1));
                    r1p[p0] = __uint_as_float(f2tf(v2));
                    r1p[p1] = __uint_as_float(f2tf(v3));
                } else {                // V: transposed, s-permuted, rounded
                    const int sp0 = (ss0 & ~63) + cpd(ss0 & 63);
                    const int sp1 = (ss1 & ~63) + cpd(ss1 & 63);
                    float* base0 = &C[((size_t)bh0 * 64 + dd) * SEQ];
                    float* base1 = &C[((size_t)bh1 * 64 + dd) * SEQ];
                    base0[sp0]       = __uint_as_float(f2tf(v0));
                    base0[SEQ + sp0] = __uint_as_float(f2tf(v1));
                    base1[sp1]       = __uint_as_float(f2tf(v2));
                    base1[SEQ + sp1] = __uint_as_float(f2tf(v3));
                }
            }
        }
    }
}

// ---------------------------------------------------------------------------
// Flash attention, tf32 MMA. 256 threads, 8 warps x 16 q-rows = 128 q-rows.
// 64-key tiles. K/V arrive pre-packed + pre-rounded from the GEMMs, so
// staging is a pure float4 copy and every B-fragment pair is one LDS.128.
// ---------------------------------------------------------------------------
__global__ __launch_bounds__(256)
void attn_tc_kernel(const float* __restrict__ Q, const float* __restrict__ Km,
                    const float* __restrict__ V, float* __restrict__ O)
{
    __shared__ float Kf[64 * 80];
    __shared__ float Vf[64 * 80];

    const int bh = blockIdx.y;
    const int NT = SEQ / 128;                    // 32 q-tiles
    const int xt = blockIdx.x;
    const int qtile = (xt & 1) ? (NT - 1 - (xt >> 1)) : (xt >> 1);
    const int qb = qtile * 128;

    const int tid = threadIdx.x;
    const int lane = tid & 31;
    const int warp = tid >> 5;
    const int gr = lane >> 2;
    const int gc = lane & 3;
    const int qrow0 = qb + warp * 16 + gr;       // rows qrow0, qrow0+8

    const float* Qb = Q  + (size_t)bh * SEQ * HDIM;
    const float* Kb = Km + (size_t)bh * SEQ * HDIM;
    const float* Vb = V  + (size_t)bh * HDIM * SEQ;

    // Q fragments: already tf32-rounded and scaled by 0.125*log2(e)
    const unsigned* Qu = (const unsigned*)Qb;
    unsigned qf[8][4];
    #pragma unroll
    for (int kc = 0; kc < 8; kc++) {
        qf[kc][0] = Qu[(size_t)qrow0 * 64 + kc * 8 + gc];
        qf[kc][1] = Qu[(size_t)(qrow0 + 8) * 64 + kc * 8 + gc];
        qf[kc][2] = Qu[(size_t)qrow0 * 64 + kc * 8 + gc + 4];
        qf[kc][3] = Qu[(size_t)(qrow0 + 8) * 64 + kc * 8 + gc + 4];
    }

    float o[8][4];
    #pragma unroll
    for (int dt = 0; dt < 8; dt++)
        #pragma unroll
        for (int j = 0; j < 4; j++) o[dt][j] = 0.f;
    float m0 = -1e30f, m1 = -1e30f, l0 = 0.f, l1 = 0.f;

    const int ntiles = qb / 64 + 2;

    for (int kt = 0; kt < ntiles; kt++) {
        // ---- stage K/V tiles: straight float4 copies ----
        #pragma unroll
        for (int i = 0; i < 4; i++) {
            const int idx = tid + i * 256;
            const int r = idx >> 4;              // K: key row / V: d row
            const int c4 = (idx & 15) * 4;
            float4 kv = *(const float4*)(Kb + (size_t)(kt * 64 + r) * 64 + c4);
            float4 vv = *(const float4*)(Vb + (size_t)r * SEQ + kt * 64 + c4);
            *(float4*)&Kf[r * 80 + c4] = kv;
            *(float4*)&Vf[r * 80 + c4] = vv;
        }
        __syncthreads();

        // ---- S = Q K^T ----
        float s[8][4];
        #pragma unroll
        for (int nt = 0; nt < 8; nt++)
            #pragma unroll
            for (int j = 0; j < 4; j++) s[nt][j] = 0.f;

        #pragma unroll
        for (int kcp = 0; kcp < 4; kcp++) {
            #pragma unroll
            for (int nt = 0; nt < 8; nt++) {
                float4 kb = *(const float4*)&Kf[(nt * 8 + gr) * 80 + kcp * 16 + gc * 4];
                mma_tf32(s[nt][0], s[nt][1], s[nt][2], s[nt][3],
                         qf[2 * kcp][0], qf[2 * kcp][1], qf[2 * kcp][2], qf[2 * kcp][3],
                         __float_as_uint(kb.x), __float_as_uint(kb.y));
                mma_tf32(s[nt][0], s[nt][1], s[nt][2], s[nt][3],
                         qf[2 * kcp + 1][0], qf[2 * kcp + 1][1],
                         qf[2 * kcp + 1][2], qf[2 * kcp + 1][3],
                         __float_as_uint(kb.z), __float_as_uint(kb.w));
            }
        }

        // ---- causal mask (last two key tiles cross the diagonal) ----
        if (kt >= ntiles - 2) {
            #pragma unroll
            for (int nt = 0; nt < 8; nt++) {
                const int col = kt * 64 + nt * 8 + 2 * gc;
                if (col > qrow0)          s[nt][0] = -1e30f;
                if (col + 1 > qrow0)      s[nt][1] = -1e30f;
                if (col > qrow0 + 8)      s[nt][2] = -1e30f;
                if (col + 1 > qrow0 + 8)  s[nt][3] = -1e30f;
            }
        }

        // ---- online softmax (base-2 domain) ----
        float tm0 = -1e30f, tm1 = -1e30f;
        #pragma unroll
        for (int nt = 0; nt < 8; nt++) {
            tm0 = fmaxf(tm0, fmaxf(s[nt][0], s[nt][1]));
            tm1 = fmaxf(tm1, fmaxf(s[nt][2], s[nt][3]));
        }
        tm0 = fmaxf(tm0, __shfl_xor_sync(FULLM, tm0, 1, 4));
        tm0 = fmaxf(tm0, __shfl_xor_sync(FULLM, tm0, 2, 4));
        tm1 = fmaxf(tm1, __shfl_xor_sync(FULLM, tm1, 1, 4));
        tm1 = fmaxf(tm1, __shfl_xor_sync(FULLM, tm1, 2, 4));

        const float nm0 = fmaxf(m0, tm0);
        const float nm1 = fmaxf(m1, tm1);
        const float sc0 = ex2(m0 - nm0);
        const float sc1 = ex2(m1 - nm1);

        float r0 = 0.f, r1 = 0.f;
        #pragma unroll
        for (int nt = 0; nt < 8; nt++) {
            s[nt][0] = ex2(s[nt][0] - nm0);
            s[nt][1] = ex2(s[nt][1] - nm0);
            s[nt][2] = ex2(s[nt][2] - nm1);
            s[nt][3] = ex2(s[nt][3] - nm1);
            r0 += s[nt][0] + s[nt][1];
            r1 += s[nt][2] + s[nt][3];
        }
        r0 += __shfl_xor_sync(FULLM, r0, 1, 4);
        r0 += __shfl_xor_sync(FULLM, r0, 2, 4);
        r1 += __shfl_xor_sync(FULLM, r1, 1, 4);
        r1 += __shfl_xor_sync(FULLM, r1, 2, 4);
        l0 = l0 * sc0 + r0;
        l1 = l1 * sc1 + r1;

        #pragma unroll
        for (int dt = 0; dt < 8; dt++) {
            o[dt][0] *= sc0; o[dt][1] *= sc0;
            o[dt][2] *= sc1; o[dt][3] *= sc1;
        }

        // ---- O += P V ----
        const int srcA = gc >> 1;
        const int srcB = srcA + 2;
        const bool odd = (gc & 1);
        #pragma unroll
        for (int kcp = 0; kcp < 4; kcp++) {
            unsigned af[2][4];
            #pragma unroll
            for (int j = 0; j < 2; j++) {
                const int kc = 2 * kcp + j;
                float t0 = __shfl_sync(FULLM, s[kc][0], srcA, 4);
                float t1 = __shfl_sync(FULLM, s[kc][1], srcA, 4);
                float t2 = __shfl_sync(FULLM, s[kc][2], srcA, 4);
                float t3 = __shfl_sync(FULLM, s[kc][3], srcA, 4);
                float u0 = __shfl_sync(FULLM, s[kc][0], srcB, 4);
                float u1 = __shfl_sync(FULLM, s[kc][1], srcB, 4);
                float u2 = __shfl_sync(FULLM, s[kc][2], srcB, 4);
                float u3 = __shfl_sync(FULLM, s[kc][3], srcB, 4);
                af[j][0] = f2tf(odd ? t1 : t0);
                af[j][1] = f2tf(odd ? t3 : t2);
                af[j][2] = f2tf(odd ? u1 : u0);
                af[j][3] = f2tf(odd ? u3 : u2);
            }
            #pragma unroll
            for (int dt = 0; dt < 8; dt++) {
                float4 vb = *(const float4*)&Vf[(dt * 8 + gr) * 80 + kcp * 16 + gc * 4];
                mma_tf32(o[dt][0], o[dt][1], o[dt][2], o[dt][3],
                         af[0][0], af[0][1], af[0][2], af[0][3],
                         __float_as_uint(vb.x), __float_as_uint(vb.y));
                mma_tf32(o[dt][0], o[dt][1], o[dt][2], o[dt][3],
                         af[1][0], af[1][1], af[1][2], af[1][3],
                         __float_as_uint(vb.z), __float_as_uint(vb.w));
            }
        }

        m0 = nm0; m1 = nm1;
        __syncthreads();
    }

    // ---- epilogue: normalize, store to [B, S, H*DH] ----
    const float inv0 = 1.f / l0;
    const float inv1 = 1.f / l1;
    const int b = bh >> 3, h = bh & 7;
    #pragma unroll
    for (int dt = 0; dt < 8; dt++) {
        const int col = dt * 8 + 2 * gc;
        *(float2*)&O[(((size_t)b * SEQ + qrow0) * NHEAD + h) * HDIM + col] =
            make_float2(o[dt][0] * inv0, o[dt][1] * inv0);
        *(float2*)&O[(((size_t)b * SEQ + qrow0 + 8) * NHEAD + h) * HDIM + col] =
            make_float2(o[dt][2] * inv1, o[dt][3] * inv1);
    }
}

// ---------------------------------------------------------------------------
extern "C" void kernel_launch(void* const* d_in, const int* in_sizes, int n_in,
                              void* d_out, int out_size)
{
    const float* x  = (const float*)d_in[0];
    const float* Wq = (const float*)d_in[1];
    const float* Wk = (const float*)d_in[2];
    const float* Wv = (const float*)d_in[3];
    const float* Wp = (const float*)d_in[4];
    const float* bp = (const float*)d_in[5];
    float* out = (float*)d_out;

    float *qp, *kp, *vp, *ap;
    cudaGetSymbolAddress((void**)&qp, g_q);
    cudaGetSymbolAddress((void**)&kp, g_k);
    cudaGetSymbolAddress((void**)&vp, g_v);
    cudaGetSymbolAddress((void**)&ap, g_attn);

    dim3 gg(BATCH * SEQ / 128, DMODEL / 64);   // (64, 8)
    gemm_tf32_kernel<<<gg, 256>>>(x, Wq, nullptr, qp, 1);
    gemm_tf32_kernel<<<gg, 256>>>(x, Wk, nullptr, kp, 2);
    gemm_tf32_kernel<<<gg, 256>>>(x, Wv, nullptr, vp, 3);

    dim3 ga(SEQ / 128, BATCH * NHEAD);          // (32, 16)
    attn_tc_kernel<<<ga, 256>>>(qp, kp, vp, ap);

    gemm_tf32_kernel<<<gg, 256>>>(ap, Wp, bp, out, 0);
}

// round 7
// speedup vs baseline: 1.1973x; 1.0611x over previous
#include <cuda_runtime.h>
#include <cstdint>

#define BATCH 2
#define SEQ   4096
#define DMODEL 512
#define NHEAD 8
#define HDIM  64
#define FULLM 0xffffffffu

// Scratch (allocation-free rule: __device__ globals)
__device__ float g_q[BATCH * NHEAD * SEQ * HDIM];   // [bh][s][d]  tf32, pre-scaled
__device__ float g_k[BATCH * NHEAD * SEQ * HDIM];   // [bh][s][cp(d)]  tf32
__device__ float g_v[BATCH * NHEAD * SEQ * HDIM];   // [bh][d][(s/64)*64+cp(s%64)] tf32
__device__ float g_attn[BATCH * SEQ * DMODEL];

__device__ __forceinline__ unsigned f2tf(float f) {
    unsigned u;
    asm("cvt.rna.tf32.f32 %0, %1;" : "=r"(u) : "f"(f));
    return u;
}

__device__ __forceinline__ float ex2(float x) {
    float r;
    asm("ex2.approx.f32 %0, %1;" : "=f"(r) : "f"(x));
    return r;
}

// fragment permutation within a 64-chunk
__device__ __forceinline__ int cpd(int i) {
    return ((i >> 4) << 4) + ((i & 3) << 2) + (((i >> 3) & 1) << 1) + ((i >> 2) & 1);
}

__device__ __forceinline__ void mma_tf32(
    float& d0, float& d1, float& d2, float& d3,
    unsigned a0, unsigned a1, unsigned a2, unsigned a3,
    unsigned b0, unsigned b1)
{
    asm volatile(
        "mma.sync.aligned.m16n8k8.row.col.f32.tf32.tf32.f32 "
        "{%0,%1,%2,%3}, {%4,%5,%6,%7}, {%8,%9}, {%0,%1,%2,%3};"
        : "+f"(d0), "+f"(d1), "+f"(d2), "+f"(d3)
        : "r"(a0), "r"(a1), "r"(a2), "r"(a3), "r"(b0), "r"(b1));
}

// ---------------------------------------------------------------------------
// tf32 NT GEMM (unchanged from R5)
// ---------------------------------------------------------------------------
__global__ __launch_bounds__(256, 2)
void gemm_tf32_kernel(const float* __restrict__ A, const float* __restrict__ W,
                      const float* __restrict__ bias, float* __restrict__ C,
                      int mode)
{
    __shared__ float As[128][36];
    __shared__ float Bs[64][36];

    const int bm = blockIdx.x * 128;
    const int bn = blockIdx.y * 64;
    const int tid = threadIdx.x;
    const int lane = tid & 31;
    const int warp = tid >> 5;
    const int gr = lane >> 2;
    const int gc = lane & 3;
    const int wm = (warp >> 1) * 32;
    const int wn = (warp & 1) * 32;

    float c[2][4][4] = {};

    for (int k0 = 0; k0 < 512; k0 += 32) {
        #pragma unroll
        for (int i = 0; i < 4; i++) {
            int idx = tid + i * 256;
            int r = idx >> 3, c4 = (idx & 7) * 4;
            float4 v = *(const float4*)(A + (size_t)(bm + r) * 512 + k0 + c4);
            float4 o;
            o.x = __uint_as_float(f2tf(v.x)); o.y = __uint_as_float(f2tf(v.y));
            o.z = __uint_as_float(f2tf(v.z)); o.w = __uint_as_float(f2tf(v.w));
            *(float4*)&As[r][c4] = o;
        }
        #pragma unroll
        for (int i = 0; i < 2; i++) {
            int idx = tid + i * 256;
            int r = idx >> 3, c4 = (idx & 7) * 4;
            float4 v = *(const float4*)(W + (size_t)(bn + r) * 512 + k0 + c4);
            float4 o;
            o.x = __uint_as_float(f2tf(v.x)); o.y = __uint_as_float(f2tf(v.y));
            o.z = __uint_as_float(f2tf(v.z)); o.w = __uint_as_float(f2tf(v.w));
            *(float4*)&Bs[r][c4] = o;
        }
        __syncthreads();

        #pragma unroll
        for (int kk = 0; kk < 4; kk++) {
            const int kc = kk * 8 + gc;
            unsigned a[2][4], b[4][2];
            #pragma unroll
            for (int mt = 0; mt < 2; mt++) {
                int r = wm + mt * 16 + gr;
                a[mt][0] = __float_as_uint(As[r][kc]);
                a[mt][1] = __float_as_uint(As[r + 8][kc]);
                a[mt][2] = __float_as_uint(As[r][kc + 4]);
                a[mt][3] = __float_as_uint(As[r + 8][kc + 4]);
            }
            #pragma unroll
            for (int nt = 0; nt < 4; nt++) {
                int r = wn + nt * 8 + gr;
                b[nt][0] = __float_as_uint(Bs[r][kc]);
                b[nt][1] = __float_as_uint(Bs[r][kc + 4]);
            }
            #pragma unroll
            for (int mt = 0; mt < 2; mt++)
                #pragma unroll
                for (int nt = 0; nt < 4; nt++)
                    mma_tf32(c[mt][nt][0], c[mt][nt][1], c[mt][nt][2], c[mt][nt][3],
                             a[mt][0], a[mt][1], a[mt][2], a[mt][3],
                             b[nt][0], b[nt][1]);
        }
        __syncthreads();
    }

    const float qs = 0.125f * 1.4426950408889634f;

    #pragma unroll
    for (int mt = 0; mt < 2; mt++) {
        #pragma unroll
        for (int nt = 0; nt < 4; nt++) {
            const int r0 = bm + wm + mt * 16 + gr;
            const int e0 = bn + wn + nt * 8 + 2 * gc;
            float v0 = c[mt][nt][0], v1 = c[mt][nt][1];
            float v2 = c[mt][nt][2], v3 = c[mt][nt][3];
            if (mode == 0) {
                const float b0 = bias[e0], b1 = bias[e0 + 1];
                *(float2*)&C[(size_t)r0 * 512 + e0]       = make_float2(v0 + b0, v1 + b1);
                *(float2*)&C[(size_t)(r0 + 8) * 512 + e0] = make_float2(v2 + b0, v3 + b1);
            } else {
                const int hh = e0 >> 6, dd = e0 & 63;
                const int bh0 = (r0 / SEQ) * NHEAD + hh;
                const int ss0 = r0 % SEQ;
                const int bh1 = ((r0 + 8) / SEQ) * NHEAD + hh;
                const int ss1 = (r0 + 8) % SEQ;
                if (mode == 1) {        // Q: normal layout, scaled + rounded
                    *(float2*)&C[((size_t)bh0 * SEQ + ss0) * 64 + dd] =
                        make_float2(__uint_as_float(f2tf(v0 * qs)),
                                    __uint_as_float(f2tf(v1 * qs)));
                    *(float2*)&C[((size_t)bh1 * SEQ + ss1) * 64 + dd] =
                        make_float2(__uint_as_float(f2tf(v2 * qs)),
                                    __uint_as_float(f2tf(v3 * qs)));
                } else if (mode == 2) { // K: d-permuted rows, rounded
                    const int p0 = cpd(dd), p1 = cpd(dd + 1);
                    float* r0p = &C[((size_t)bh0 * SEQ + ss0) * 64];
                    float* r1p = &C[((size_t)bh1 * SEQ + ss1) * 64];
                    r0p[p0] = __uint_as_float(f2tf(v0));
                    r0p[p1] = __uint_as_float(f2tf(v1));
                    r1p[p0] = __uint_as_float(f2tf(v2));
                    r1p[p1] = __uint_as_float(f2tf(v3));
                } else {                // V: transposed, s-permuted, rounded
                    const int sp0 = (ss0 & ~63) + cpd(ss0 & 63);
                    const int sp1 = (ss1 & ~63) + cpd(ss1 & 63);
                    float* base0 = &C[((size_t)bh0 * 64 + dd) * SEQ];
                    float* base1 = &C[((size_t)bh1 * 64 + dd) * SEQ];
                    base0[sp0]       = __uint_as_float(f2tf(v0));
                    base0[SEQ + sp0] = __uint_as_float(f2tf(v1));
                    base1[sp1]       = __uint_as_float(f2tf(v2));
                    base1[SEQ + sp1] = __uint_as_float(f2tf(v3));
                }
            }
        }
    }
}

// ---------------------------------------------------------------------------
// Flash attention, tf32 MMA. 256 threads, 8 warps x 16 q-rows.
// Q fragments manually "spilled" to a per-lane smem array (no cross-lane
// sharing -> no sync, conflict-free float4 reload) to fit 2 CTAs/SM.
// Dynamic smem: Kf(20KB) + Vf(20KB) + Qs(32KB) = 72KB.
// ---------------------------------------------------------------------------
#define ATTN_SMEM (2 * 64 * 80 * 4 + 8 * 8 * 32 * 16)

__global__ __launch_bounds__(256, 2)
void attn_tc_kernel(const float* __restrict__ Q, const float* __restrict__ Km,
                    const float* __restrict__ V, float* __restrict__ O)
{
    extern __shared__ float dsm[];
    float* Kf = dsm;                         // 64*80
    float* Vf = dsm + 64 * 80;               // 64*80
    float4* Qs = (float4*)(dsm + 2 * 64 * 80); // [8 warps][8 kc][32 lanes]

    const int bh = blockIdx.y;
    const int NT = SEQ / 128;
    const int xt = blockIdx.x;
    const int qtile = (xt & 1) ? (NT - 1 - (xt >> 1)) : (xt >> 1);
    const int qb = qtile * 128;

    const int tid = threadIdx.x;
    const int lane = tid & 31;
    const int warp = tid >> 5;
    const int gr = lane >> 2;
    const int gc = lane & 3;
    const int qrow0 = qb + warp * 16 + gr;

    const float* Qb = Q  + (size_t)bh * SEQ * HDIM;
    const float* Kb = Km + (size_t)bh * SEQ * HDIM;
    const float* Vb = V  + (size_t)bh * HDIM * SEQ;

    // stage this lane's Q fragments (pre-scaled tf32) into its private smem slot
    {
        const unsigned* Qu = (const unsigned*)Qb;
        #pragma unroll
        for (int kc = 0; kc < 8; kc++) {
            float4 f;
            f.x = __uint_as_float(Qu[(size_t)qrow0 * 64 + kc * 8 + gc]);
            f.y = __uint_as_float(Qu[(size_t)(qrow0 + 8) * 64 + kc * 8 + gc]);
            f.z = __uint_as_float(Qu[(size_t)qrow0 * 64 + kc * 8 + gc + 4]);
            f.w = __uint_as_float(Qu[(size_t)(qrow0 + 8) * 64 + kc * 8 + gc + 4]);
            Qs[(warp * 8 + kc) * 32 + lane] = f;
        }
    }

    float o[8][4];
    #pragma unroll
    for (int dt = 0; dt < 8; dt++)
        #pragma unroll
        for (int j = 0; j < 4; j++) o[dt][j] = 0.f;
    float m0 = -1e30f, m1 = -1e30f, l0 = 0.f, l1 = 0.f;

    const int ntiles = qb / 64 + 2;

    for (int kt = 0; kt < ntiles; kt++) {
        // ---- stage K/V tiles: straight float4 copies ----
        #pragma unroll
        for (int i = 0; i < 4; i++) {
            const int idx = tid + i * 256;
            const int r = idx >> 4;
            const int c4 = (idx & 15) * 4;
            float4 kv = *(const float4*)(Kb + (size_t)(kt * 64 + r) * 64 + c4);
            float4 vv = *(const float4*)(Vb + (size_t)r * SEQ + kt * 64 + c4);
            *(float4*)&Kf[r * 80 + c4] = kv;
            *(float4*)&Vf[r * 80 + c4] = vv;
        }
        __syncthreads();

        // ---- S = Q K^T ----
        float s[8][4];
        #pragma unroll
        for (int nt = 0; nt < 8; nt++)
            #pragma unroll
            for (int j = 0; j < 4; j++) s[nt][j] = 0.f;

        #pragma unroll
        for (int kcp = 0; kcp < 4; kcp++) {
            const float4 qa = Qs[(warp * 8 + 2 * kcp) * 32 + lane];
            const float4 qb4 = Qs[(warp * 8 + 2 * kcp + 1) * 32 + lane];
            #pragma unroll
            for (int nt = 0; nt < 8; nt++) {
                float4 kb = *(const float4*)&Kf[(nt * 8 + gr) * 80 + kcp * 16 + gc * 4];
                mma_tf32(s[nt][0], s[nt][1], s[nt][2], s[nt][3],
                         __float_as_uint(qa.x), __float_as_uint(qa.y),
                         __float_as_uint(qa.z), __float_as_uint(qa.w),
                         __float_as_uint(kb.x), __float_as_uint(kb.y));
                mma_tf32(s[nt][0], s[nt][1], s[nt][2], s[nt][3],
                         __float_as_uint(qb4.x), __float_as_uint(qb4.y),
                         __float_as_uint(qb4.z), __float_as_uint(qb4.w),
                         __float_as_uint(kb.z), __float_as_uint(kb.w));
            }
        }

        // ---- causal mask ----
        if (kt >= ntiles - 2) {
            #pragma unroll
            for (int nt = 0; nt < 8; nt++) {
                const int col = kt * 64 + nt * 8 + 2 * gc;
                if (col > qrow0)          s[nt][0] = -1e30f;
                if (col + 1 > qrow0)      s[nt][1] = -1e30f;
                if (col > qrow0 + 8)      s[nt][2] = -1e30f;
                if (col + 1 > qrow0 + 8)  s[nt][3] = -1e30f;
            }
        }

        // ---- online softmax (base-2 domain) ----
        float tm0 = -1e30f, tm1 = -1e30f;
        #pragma unroll
        for (int nt = 0; nt < 8; nt++) {
            tm0 = fmaxf(tm0, fmaxf(s[nt][0], s[nt][1]));
            tm1 = fmaxf(tm1, fmaxf(s[nt][2], s[nt][3]));
        }
        tm0 = fmaxf(tm0, __shfl_xor_sync(FULLM, tm0, 1, 4));
        tm0 = fmaxf(tm0, __shfl_xor_sync(FULLM, tm0, 2, 4));
        tm1 = fmaxf(tm1, __shfl_xor_sync(FULLM, tm1, 1, 4));
        tm1 = fmaxf(tm1, __shfl_xor_sync(FULLM, tm1, 2, 4));

        const float nm0 = fmaxf(m0, tm0);
        const float nm1 = fmaxf(m1, tm1);
        const float sc0 = ex2(m0 - nm0);
        const float sc1 = ex2(m1 - nm1);

        float r0 = 0.f, r1 = 0.f;
        #pragma unroll
        for (int nt = 0; nt < 8; nt++) {
            s[nt][0] = ex2(s[nt][0] - nm0);
            s[nt][1] = ex2(s[nt][1] - nm0);
            s[nt][2] = ex2(s[nt][2] - nm1);
            s[nt][3] = ex2(s[nt][3] - nm1);
            r0 += s[nt][0] + s[nt][1];
            r1 += s[nt][2] + s[nt][3];
        }
        r0 += __shfl_xor_sync(FULLM, r0, 1, 4);
        r0 += __shfl_xor_sync(FULLM, r0, 2, 4);
        r1 += __shfl_xor_sync(FULLM, r1, 1, 4);
        r1 += __shfl_xor_sync(FULLM, r1, 2, 4);
        l0 = l0 * sc0 + r0;
        l1 = l1 * sc1 + r1;

        #pragma unroll
        for (int dt = 0; dt < 8; dt++) {
            o[dt][0] *= sc0; o[dt][1] *= sc0;
            o[dt][2] *= sc1; o[dt][3] *= sc1;
        }

        // ---- O += P V ----
        const int srcA = gc >> 1;
        const int srcB = srcA + 2;
        const bool odd = (gc & 1);
        #pragma unroll
        for (int kcp = 0; kcp < 4; kcp++) {
            unsigned af[2][4];
            #pragma unroll
            for (int j = 0; j < 2; j++) {
                const int kc = 2 * kcp + j;
                float t0 = __shfl_sync(FULLM, s[kc][0], srcA, 4);
                float t1 = __shfl_sync(FULLM, s[kc][1], srcA, 4);
                float t2 = __shfl_sync(FULLM, s[kc][2], srcA, 4);
                float t3 = __shfl_sync(FULLM, s[kc][3], srcA, 4);
                float u0 = __shfl_sync(FULLM, s[kc][0], srcB, 4);
                float u1 = __shfl_sync(FULLM, s[kc][1], srcB, 4);
                float u2 = __shfl_sync(FULLM, s[kc][2], srcB, 4);
                float u3 = __shfl_sync(FULLM, s[kc][3], srcB, 4);
                af[j][0] = f2tf(odd ? t1 : t0);
                af[j][1] = f2tf(odd ? t3 : t2);
                af[j][2] = f2tf(odd ? u1 : u0);
                af[j][3] = f2tf(odd ? u3 : u2);
            }
            #pragma unroll
            for (int dt = 0; dt < 8; dt++) {
                float4 vb = *(const float4*)&Vf[(dt * 8 + gr) * 80 + kcp * 16 + gc * 4];
                mma_tf32(o[dt][0], o[dt][1], o[dt][2], o[dt][3],
                         af[0][0], af[0][1], af[0][2], af[0][3],
                         __float_as_uint(vb.x), __float_as_uint(vb.y));
                mma_tf32(o[dt][0], o[dt][1], o[dt][2], o[dt][3],
                         af[1][0], af[1][1], af[1][2], af[1][3],
                         __float_as_uint(vb.z), __float_as_uint(vb.w));
            }
        }

        m0 = nm0; m1 = nm1;
        __syncthreads();
    }

    // ---- epilogue ----
    const float inv0 = 1.f / l0;
    const float inv1 = 1.f / l1;
    const int b = bh >> 3, h = bh & 7;
    #pragma unroll
    for (int dt = 0; dt < 8; dt++) {
        const int col = dt * 8 + 2 * gc;
        *(float2*)&O[(((size_t)b * SEQ + qrow0) * NHEAD + h) * HDIM + col] =
            make_float2(o[dt][0] * inv0, o[dt][1] * inv0);
        *(float2*)&O[(((size_t)b * SEQ + qrow0 + 8) * NHEAD + h) * HDIM + col] =
            make_float2(o[dt][2] * inv1, o[dt][3] * inv1);
    }
}

// ---------------------------------------------------------------------------
extern "C" void kernel_launch(void* const* d_in, const int* in_sizes, int n_in,
                              void* d_out, int out_size)
{
    const float* x  = (const float*)d_in[0];
    const float* Wq = (const float*)d_in[1];
    const float* Wk = (const float*)d_in[2];
    const float* Wv = (const float*)d_in[3];
    const float* Wp = (const float*)d_in[4];
    const float* bp = (const float*)d_in[5];
    float* out = (float*)d_out;

    float *qp, *kp, *vp, *ap;
    cudaGetSymbolAddress((void**)&qp, g_q);
    cudaGetSymbolAddress((void**)&kp, g_k);
    cudaGetSymbolAddress((void**)&vp, g_v);
    cudaGetSymbolAddress((void**)&ap, g_attn);

    static int attr_set = 0;
    if (!attr_set) {
        cudaFuncSetAttribute(attn_tc_kernel,
                             cudaFuncAttributeMaxDynamicSharedMemorySize, ATTN_SMEM);
        attr_set = 1;
    }

    dim3 gg(BATCH * SEQ / 128, DMODEL / 64);   // (64, 8)
    gemm_tf32_kernel<<<gg, 256>>>(x, Wq, nullptr, qp, 1);
    gemm_tf32_kernel<<<gg, 256>>>(x, Wk, nullptr, kp, 2);
    gemm_tf32_kernel<<<gg, 256>>>(x, Wv, nullptr, vp, 3);

    dim3 ga(SEQ / 128, BATCH * NHEAD);          // (32, 16)
    attn_tc_kernel<<<ga, 256, ATTN_SMEM>>>(qp, kp, vp, ap);

    gemm_tf32_kernel<<<gg, 256>>>(ap, Wp, bp, out, 0);
}

// round 8
// speedup vs baseline: 1.2561x; 1.0491x over previous
#include <cuda_runtime.h>
#include <cstdint>

#define BATCH 2
#define SEQ   4096
#define DMODEL 512
#define NHEAD 8
#define HDIM  64
#define FULLM 0xffffffffu

// Scratch (allocation-free rule: __device__ globals)
__device__ float g_q[BATCH * NHEAD * SEQ * HDIM];   // [bh][s][d]  tf32, pre-scaled
__device__ float g_k[BATCH * NHEAD * SEQ * HDIM];   // [bh][s][cp(d)]  tf32
__device__ float g_v[BATCH * NHEAD * SEQ * HDIM];   // [bh][d][(s/64)*64+cp(s%64)] tf32
__device__ float g_attn[BATCH * SEQ * DMODEL];

__device__ __forceinline__ unsigned f2tf(float f) {
    unsigned u;
    asm("cvt.rna.tf32.f32 %0, %1;" : "=r"(u) : "f"(f));
    return u;
}

__device__ __forceinline__ float ex2(float x) {
    float r;
    asm("ex2.approx.f32 %0, %1;" : "=f"(r) : "f"(x));
    return r;
}

// fragment permutation within a 64-chunk
__device__ __forceinline__ int cpd(int i) {
    return ((i >> 4) << 4) + ((i & 3) << 2) + (((i >> 3) & 1) << 1) + ((i >> 2) & 1);
}

__device__ __forceinline__ void mma_tf32(
    float& d0, float& d1, float& d2, float& d3,
    unsigned a0, unsigned a1, unsigned a2, unsigned a3,
    unsigned b0, unsigned b1)
{
    asm volatile(
        "mma.sync.aligned.m16n8k8.row.col.f32.tf32.tf32.f32 "
        "{%0,%1,%2,%3}, {%4,%5,%6,%7}, {%8,%9}, {%0,%1,%2,%3};"
        : "+f"(d0), "+f"(d1), "+f"(d2), "+f"(d3)
        : "r"(a0), "r"(a1), "r"(a2), "r"(a3), "r"(b0), "r"(b1));
}

// ---------------------------------------------------------------------------
// tf32 NT GEMM (unchanged)
// ---------------------------------------------------------------------------
__global__ __launch_bounds__(256, 2)
void gemm_tf32_kernel(const float* __restrict__ A, const float* __restrict__ W,
                      const float* __restrict__ bias, float* __restrict__ C,
                      int mode)
{
    __shared__ float As[128][36];
    __shared__ float Bs[64][36];

    const int bm = blockIdx.x * 128;
    const int bn = blockIdx.y * 64;
    const int tid = threadIdx.x;
    const int lane = tid & 31;
    const int warp = tid >> 5;
    const int gr = lane >> 2;
    const int gc = lane & 3;
    const int wm = (warp >> 1) * 32;
    const int wn = (warp & 1) * 32;

    float c[2][4][4] = {};

    for (int k0 = 0; k0 < 512; k0 += 32) {
        #pragma unroll
        for (int i = 0; i < 4; i++) {
            int idx = tid + i * 256;
            int r = idx >> 3, c4 = (idx & 7) * 4;
            float4 v = *(const float4*)(A + (size_t)(bm + r) * 512 + k0 + c4);
            float4 o;
            o.x = __uint_as_float(f2tf(v.x)); o.y = __uint_as_float(f2tf(v.y));
            o.z = __uint_as_float(f2tf(v.z)); o.w = __uint_as_float(f2tf(v.w));
            *(float4*)&As[r][c4] = o;
        }
        #pragma unroll
        for (int i = 0; i < 2; i++) {
            int idx = tid + i * 256;
            int r = idx >> 3, c4 = (idx & 7) * 4;
            float4 v = *(const float4*)(W + (size_t)(bn + r) * 512 + k0 + c4);
            float4 o;
            o.x = __uint_as_float(f2tf(v.x)); o.y = __uint_as_float(f2tf(v.y));
            o.z = __uint_as_float(f2tf(v.z)); o.w = __uint_as_float(f2tf(v.w));
            *(float4*)&Bs[r][c4] = o;
        }
        __syncthreads();

        #pragma unroll
        for (int kk = 0; kk < 4; kk++) {
            const int kc = kk * 8 + gc;
            unsigned a[2][4], b[4][2];
            #pragma unroll
            for (int mt = 0; mt < 2; mt++) {
                int r = wm + mt * 16 + gr;
                a[mt][0] = __float_as_uint(As[r][kc]);
                a[mt][1] = __float_as_uint(As[r + 8][kc]);
                a[mt][2] = __float_as_uint(As[r][kc + 4]);
                a[mt][3] = __float_as_uint(As[r + 8][kc + 4]);
            }
            #pragma unroll
            for (int nt = 0; nt < 4; nt++) {
                int r = wn + nt * 8 + gr;
                b[nt][0] = __float_as_uint(Bs[r][kc]);
                b[nt][1] = __float_as_uint(Bs[r][kc + 4]);
            }
            #pragma unroll
            for (int mt = 0; mt < 2; mt++)
                #pragma unroll
                for (int nt = 0; nt < 4; nt++)
                    mma_tf32(c[mt][nt][0], c[mt][nt][1], c[mt][nt][2], c[mt][nt][3],
                             a[mt][0], a[mt][1], a[mt][2], a[mt][3],
                             b[nt][0], b[nt][1]);
        }
        __syncthreads();
    }

    const float qs = 0.125f * 1.4426950408889634f;

    #pragma unroll
    for (int mt = 0; mt < 2; mt++) {
        #pragma unroll
        for (int nt = 0; nt < 4; nt++) {
            const int r0 = bm + wm + mt * 16 + gr;
            const int e0 = bn + wn + nt * 8 + 2 * gc;
            float v0 = c[mt][nt][0], v1 = c[mt][nt][1];
            float v2 = c[mt][nt][2], v3 = c[mt][nt][3];
            if (mode == 0) {
                const float b0 = bias[e0], b1 = bias[e0 + 1];
                *(float2*)&C[(size_t)r0 * 512 + e0]       = make_float2(v0 + b0, v1 + b1);
                *(float2*)&C[(size_t)(r0 + 8) * 512 + e0] = make_float2(v2 + b0, v3 + b1);
            } else {
                const int hh = e0 >> 6, dd = e0 & 63;
                const int bh0 = (r0 / SEQ) * NHEAD + hh;
                const int ss0 = r0 % SEQ;
                const int bh1 = ((r0 + 8) / SEQ) * NHEAD + hh;
                const int ss1 = (r0 + 8) % SEQ;
                if (mode == 1) {        // Q: normal layout, scaled + rounded
                    *(float2*)&C[((size_t)bh0 * SEQ + ss0) * 64 + dd] =
                        make_float2(__uint_as_float(f2tf(v0 * qs)),
                                    __uint_as_float(f2tf(v1 * qs)));
                    *(float2*)&C[((size_t)bh1 * SEQ + ss1) * 64 + dd] =
                        make_float2(__uint_as_float(f2tf(v2 * qs)),
                                    __uint_as_float(f2tf(v3 * qs)));
                } else if (mode == 2) { // K: d-permuted rows, rounded
                    const int p0 = cpd(dd), p1 = cpd(dd + 1);
                    float* r0p = &C[((size_t)bh0 * SEQ + ss0) * 64];
                    float* r1p = &C[((size_t)bh1 * SEQ + ss1) * 64];
                    r0p[p0] = __uint_as_float(f2tf(v0));
                    r0p[p1] = __uint_as_float(f2tf(v1));
                    r1p[p0] = __uint_as_float(f2tf(v2));
                    r1p[p1] = __uint_as_float(f2tf(v3));
                } else {                // V: transposed, s-permuted, rounded
                    const int sp0 = (ss0 & ~63) + cpd(ss0 & 63);
                    const int sp1 = (ss1 & ~63) + cpd(ss1 & 63);
                    float* base0 = &C[((size_t)bh0 * 64 + dd) * SEQ];
                    float* base1 = &C[((size_t)bh1 * 64 + dd) * SEQ];
                    base0[sp0]       = __uint_as_float(f2tf(v0));
                    base0[SEQ + sp0] = __uint_as_float(f2tf(v1));
                    base1[sp1]       = __uint_as_float(f2tf(v2));
                    base1[SEQ + sp1] = __uint_as_float(f2tf(v3));
                }
            }
        }
    }
}

// ---------------------------------------------------------------------------
// Flash attention, tf32 MMA. 128 threads = 4 warps x 32 q-rows (two 16-row
// m-blocks per warp) = 128 q-rows per CTA. Each K/V B-fragment LDS.128 now
// feeds 4 MMAs (shared across both m-blocks) -> smem bandwidth per MMA halved.
// Dynamic smem: Kf(20KB) + Vf(20KB) + Qs(32KB) = 72KB; 2 CTAs/SM.
// ---------------------------------------------------------------------------
#define ATTN_SMEM (2 * 64 * 80 * 4 + 4 * 2 * 8 * 32 * 16)

__global__ __launch_bounds__(128, 2)
void attn_tc_kernel(const float* __restrict__ Q, const float* __restrict__ Km,
                    const float* __restrict__ V, float* __restrict__ O)
{
    extern __shared__ float dsm[];
    float* Kf = dsm;                           // 64*80
    float* Vf = dsm + 64 * 80;                 // 64*80
    float4* Qs = (float4*)(dsm + 2 * 64 * 80); // [4 warps][2 mb][8 kc][32 lanes]

    const int bh = blockIdx.y;
    const int NT = SEQ / 128;
    const int xt = blockIdx.x;
    const int qtile = (xt & 1) ? (NT - 1 - (xt >> 1)) : (xt >> 1);
    const int qb = qtile * 128;

    const int tid = threadIdx.x;
    const int lane = tid & 31;
    const int warp = tid >> 5;
    const int gr = lane >> 2;
    const int gc = lane & 3;
    // warp covers rows [qb + warp*32, qb + warp*32 + 32)
    const int qr[2] = { qb + warp * 32 + gr, qb + warp * 32 + 16 + gr };

    const float* Qb = Q  + (size_t)bh * SEQ * HDIM;
    const float* Kb = Km + (size_t)bh * SEQ * HDIM;
    const float* Vb = V  + (size_t)bh * HDIM * SEQ;

    // stage this lane's Q fragments (pre-scaled tf32) into private smem slots
    {
        const unsigned* Qu = (const unsigned*)Qb;
        #pragma unroll
        for (int mb = 0; mb < 2; mb++) {
            #pragma unroll
            for (int kc = 0; kc < 8; kc++) {
                float4 f;
                f.x = __uint_as_float(Qu[(size_t)qr[mb] * 64 + kc * 8 + gc]);
                f.y = __uint_as_float(Qu[(size_t)(qr[mb] + 8) * 64 + kc * 8 + gc]);
                f.z = __uint_as_float(Qu[(size_t)qr[mb] * 64 + kc * 8 + gc + 4]);
                f.w = __uint_as_float(Qu[(size_t)(qr[mb] + 8) * 64 + kc * 8 + gc + 4]);
                Qs[((warp * 2 + mb) * 8 + kc) * 32 + lane] = f;
            }
        }
    }

    float o[2][8][4];
    #pragma unroll
    for (int mb = 0; mb < 2; mb++)
        #pragma unroll
        for (int dt = 0; dt < 8; dt++)
            #pragma unroll
            for (int j = 0; j < 4; j++) o[mb][dt][j] = 0.f;
    float mM[2][2] = {{-1e30f, -1e30f}, {-1e30f, -1e30f}};
    float lL[2][2] = {{0.f, 0.f}, {0.f, 0.f}};

    const int ntiles = qb / 64 + 2;

    for (int kt = 0; kt < ntiles; kt++) {
        // ---- stage K/V tiles: straight float4 copies ----
        #pragma unroll
        for (int i = 0; i < 8; i++) {
            const int idx = tid + i * 128;
            const int r = idx >> 4;
            const int c4 = (idx & 15) * 4;
            float4 kv = *(const float4*)(Kb + (size_t)(kt * 64 + r) * 64 + c4);
            float4 vv = *(const float4*)(Vb + (size_t)r * SEQ + kt * 64 + c4);
            *(float4*)&Kf[r * 80 + c4] = kv;
            *(float4*)&Vf[r * 80 + c4] = vv;
        }
        __syncthreads();

        // ---- S = Q K^T (both m-blocks share every K fragment) ----
        float s[2][8][4];
        #pragma unroll
        for (int mb = 0; mb < 2; mb++)
            #pragma unroll
            for (int nt = 0; nt < 8; nt++)
                #pragma unroll
                for (int j = 0; j < 4; j++) s[mb][nt][j] = 0.f;

        #pragma unroll
        for (int kcp = 0; kcp < 4; kcp++) {
            float4 qa[2], qb4[2];
            #pragma unroll
            for (int mb = 0; mb < 2; mb++) {
                qa[mb]  = Qs[((warp * 2 + mb) * 8 + 2 * kcp) * 32 + lane];
                qb4[mb] = Qs[((warp * 2 + mb) * 8 + 2 * kcp + 1) * 32 + lane];
            }
            #pragma unroll
            for (int nt = 0; nt < 8; nt++) {
                float4 kb = *(const float4*)&Kf[(nt * 8 + gr) * 80 + kcp * 16 + gc * 4];
                #pragma unroll
                for (int mb = 0; mb < 2; mb++) {
                    mma_tf32(s[mb][nt][0], s[mb][nt][1], s[mb][nt][2], s[mb][nt][3],
                             __float_as_uint(qa[mb].x), __float_as_uint(qa[mb].y),
                             __float_as_uint(qa[mb].z), __float_as_uint(qa[mb].w),
                             __float_as_uint(kb.x), __float_as_uint(kb.y));
                    mma_tf32(s[mb][nt][0], s[mb][nt][1], s[mb][nt][2], s[mb][nt][3],
                             __float_as_uint(qb4[mb].x), __float_as_uint(qb4[mb].y),
                             __float_as_uint(qb4[mb].z), __float_as_uint(qb4[mb].w),
                             __float_as_uint(kb.z), __float_as_uint(kb.w));
                }
            }
        }

        // ---- causal mask ----
        if (kt >= ntiles - 2) {
            #pragma unroll
            for (int mb = 0; mb < 2; mb++)
                #pragma unroll
                for (int nt = 0; nt < 8; nt++) {
                    const int col = kt * 64 + nt * 8 + 2 * gc;
                    if (col > qr[mb])          s[mb][nt][0] = -1e30f;
                    if (col + 1 > qr[mb])      s[mb][nt][1] = -1e30f;
                    if (col > qr[mb] + 8)      s[mb][nt][2] = -1e30f;
                    if (col + 1 > qr[mb] + 8)  s[mb][nt][3] = -1e30f;
                }
        }

        // ---- online softmax (base-2 domain) ----
        #pragma unroll
        for (int mb = 0; mb < 2; mb++) {
            float tm0 = -1e30f, tm1 = -1e30f;
            #pragma unroll
            for (int nt = 0; nt < 8; nt++) {
                tm0 = fmaxf(tm0, fmaxf(s[mb][nt][0], s[mb][nt][1]));
                tm1 = fmaxf(tm1, fmaxf(s[mb][nt][2], s[mb][nt][3]));
            }
            tm0 = fmaxf(tm0, __shfl_xor_sync(FULLM, tm0, 1, 4));
            tm0 = fmaxf(tm0, __shfl_xor_sync(FULLM, tm0, 2, 4));
            tm1 = fmaxf(tm1, __shfl_xor_sync(FULLM, tm1, 1, 4));
            tm1 = fmaxf(tm1, __shfl_xor_sync(FULLM, tm1, 2, 4));

            const float nm0 = fmaxf(mM[mb][0], tm0);
            const float nm1 = fmaxf(mM[mb][1], tm1);
            const float sc0 = ex2(mM[mb][0] - nm0);
            const float sc1 = ex2(mM[mb][1] - nm1);

            float r0 = 0.f, r1 = 0.f;
            #pragma unroll
            for (int nt = 0; nt < 8; nt++) {
                s[mb][nt][0] = ex2(s[mb][nt][0] - nm0);
                s[mb][nt][1] = ex2(s[mb][nt][1] - nm0);
                s[mb][nt][2] = ex2(s[mb][nt][2] - nm1);
                s[mb][nt][3] = ex2(s[mb][nt][3] - nm1);
                r0 += s[mb][nt][0] + s[mb][nt][1];
                r1 += s[mb][nt][2] + s[mb][nt][3];
            }
            r0 += __shfl_xor_sync(FULLM, r0, 1, 4);
            r0 += __shfl_xor_sync(FULLM, r0, 2, 4);
            r1 += __shfl_xor_sync(FULLM, r1, 1, 4);
            r1 += __shfl_xor_sync(FULLM, r1, 2, 4);
            lL[mb][0] = lL[mb][0] * sc0 + r0;
            lL[mb][1] = lL[mb][1] * sc1 + r1;

            #pragma unroll
            for (int dt = 0; dt < 8; dt++) {
                o[mb][dt][0] *= sc0; o[mb][dt][1] *= sc0;
                o[mb][dt][2] *= sc1; o[mb][dt][3] *= sc1;
            }
            mM[mb][0] = nm0; mM[mb][1] = nm1;
        }

        // ---- O += P V (both m-blocks share every V fragment) ----
        const int srcA = gc >> 1;
        const int srcB = srcA + 2;
        const bool odd = (gc & 1);
        #pragma unroll
        for (int kcp = 0; kcp < 4; kcp++) {
            unsigned af[2][2][4];
            #pragma unroll
            for (int mb = 0; mb < 2; mb++) {
                #pragma unroll
                for (int j = 0; j < 2; j++) {
                    const int kc = 2 * kcp + j;
                    float t0 = __shfl_sync(FULLM, s[mb][kc][0], srcA, 4);
                    float t1 = __shfl_sync(FULLM, s[mb][kc][1], srcA, 4);
                    float t2 = __shfl_sync(FULLM, s[mb][kc][2], srcA, 4);
                    float t3 = __shfl_sync(FULLM, s[mb][kc][3], srcA, 4);
                    float u0 = __shfl_sync(FULLM, s[mb][kc][0], srcB, 4);
                    float u1 = __shfl_sync(FULLM, s[mb][kc][1], srcB, 4);
                    float u2 = __shfl_sync(FULLM, s[mb][kc][2], srcB, 4);
                    float u3 = __shfl_sync(FULLM, s[mb][kc][3], srcB, 4);
                    af[mb][j][0] = f2tf(odd ? t1 : t0);
                    af[mb][j][1] = f2tf(odd ? t3 : t2);
                    af[mb][j][2] = f2tf(odd ? u1 : u0);
                    af[mb][j][3] = f2tf(odd ? u3 : u2);
                }
            }
            #pragma unroll
            for (int dt = 0; dt < 8; dt++) {
                float4 vb = *(const float4*)&Vf[(dt * 8 + gr) * 80 + kcp * 16 + gc * 4];
                #pragma unroll
                for (int mb = 0; mb < 2; mb++) {
                    mma_tf32(o[mb][dt][0], o[mb][dt][1], o[mb][dt][2], o[mb][dt][3],
                             af[mb][0][0], af[mb][0][1], af[mb][0][2], af[mb][0][3],
                             __float_as_uint(vb.x), __float_as_uint(vb.y));
                    mma_tf32(o[mb][dt][0], o[mb][dt][1], o[mb][dt][2], o[mb][dt][3],
                             af[mb][1][0], af[mb][1][1], af[mb][1][2], af[mb][1][3],
                             __float_as_uint(vb.z), __float_as_uint(vb.w));
                }
            }
        }

        __syncthreads();
    }

    // ---- epilogue: normalize, store to [B, S, H*DH] ----
    const int b = bh >> 3, h = bh & 7;
    #pragma unroll
    for (int mb = 0; mb < 2; mb++) {
        const float inv0 = 1.f / lL[mb][0];
        const float inv1 = 1.f / lL[mb][1];
        #pragma unroll
        for (int dt = 0; dt < 8; dt++) {
            const int col = dt * 8 + 2 * gc;
            *(float2*)&O[(((size_t)b * SEQ + qr[mb]) * NHEAD + h) * HDIM + col] =
                make_float2(o[mb][dt][0] * inv0, o[mb][dt][1] * inv0);
            *(float2*)&O[(((size_t)b * SEQ + qr[mb] + 8) * NHEAD + h) * HDIM + col] =
                make_float2(o[mb][dt][2] * inv1, o[mb][dt][3] * inv1);
        }
    }
}

// ---------------------------------------------------------------------------
extern "C" void kernel_launch(void* const* d_in, const int* in_sizes, int n_in,
                              void* d_out, int out_size)
{
    const float* x  = (const float*)d_in[0];
    const float* Wq = (const float*)d_in[1];
    const float* Wk = (const float*)d_in[2];
    const float* Wv = (const float*)d_in[3];
    const float* Wp = (const float*)d_in[4];
    const float* bp = (const float*)d_in[5];
    float* out = (float*)d_out;

    float *qp, *kp, *vp, *ap;
    cudaGetSymbolAddress((void**)&qp, g_q);
    cudaGetSymbolAddress((void**)&kp, g_k);
    cudaGetSymbolAddress((void**)&vp, g_v);
    cudaGetSymbolAddress((void**)&ap, g_attn);

    static int attr_set = 0;
    if (!attr_set) {
        cudaFuncSetAttribute(attn_tc_kernel,
                             cudaFuncAttributeMaxDynamicSharedMemorySize, ATTN_SMEM);
        attr_set = 1;
    }

    dim3 gg(BATCH * SEQ / 128, DMODEL / 64);   // (64, 8)
    gemm_tf32_kernel<<<gg, 256>>>(x, Wq, nullptr, qp, 1);
    gemm_tf32_kernel<<<gg, 256>>>(x, Wk, nullptr, kp, 2);
    gemm_tf32_kernel<<<gg, 256>>>(x, Wv, nullptr, vp, 3);

    dim3 ga(SEQ / 128, BATCH * NHEAD);          // (32, 16)
    attn_tc_kernel<<<ga, 128, ATTN_SMEM>>>(qp, kp, vp, ap);

    gemm_tf32_kernel<<<gg, 256>>>(ap, Wp, bp, out, 0);
}

// round 13
// speedup vs baseline: 1.8317x; 1.4583x over previous
#include <cuda_runtime.h>
#include <cuda_fp16.h>
#include <cstdint>

#define BATCH 2
#define SEQ   4096
#define DMODEL 512
#define NHEAD 8
#define HDIM  64
#define FULLM 0xffffffffu

// Scratch (allocation-free rule: __device__ globals)
// Q: [bh][s][d-pairs plain]          fp16, pre-scaled by 0.125*log2e
// K: [bh][s][pair-packed d]          fp16  (b-frag pairs adjacent + XOR swizzle)
// V: [bh][d][s-tile pair-packed s]   fp16  (transposed, same packing per 64-tile)
__device__ __half g_qh[BATCH * NHEAD * SEQ * HDIM];
__device__ __half g_kh[BATCH * NHEAD * SEQ * HDIM];
__device__ __half g_vh[BATCH * NHEAD * SEQ * HDIM];
__device__ float  g_attn[BATCH * SEQ * DMODEL];

__device__ __forceinline__ unsigned f2tf(float f) {
    unsigned u;
    asm("cvt.rna.tf32.f32 %0, %1;" : "=r"(u) : "f"(f));
    return u;
}

__device__ __forceinline__ float ex2(float x) {
    float r;
    asm("ex2.approx.f32 %0, %1;" : "=f"(r) : "f"(x));
    return r;
}

__device__ __forceinline__ unsigned packh2(float lo, float hi) {
    __half2 h = __floats2half2_rn(lo, hi);
    return *(unsigned*)&h;
}

__device__ __forceinline__ void mma_tf32(
    float& d0, float& d1, float& d2, float& d3,
    unsigned a0, unsigned a1, unsigned a2, unsigned a3,
    unsigned b0, unsigned b1)
{
    asm volatile(
        "mma.sync.aligned.m16n8k8.row.col.f32.tf32.tf32.f32 "
        "{%0,%1,%2,%3}, {%4,%5,%6,%7}, {%8,%9}, {%0,%1,%2,%3};"
        : "+f"(d0), "+f"(d1), "+f"(d2), "+f"(d3)
        : "r"(a0), "r"(a1), "r"(a2), "r"(a3), "r"(b0), "r"(b1));
}

__device__ __forceinline__ void mma_f16(
    float& d0, float& d1, float& d2, float& d3,
    unsigned a0, unsigned a1, unsigned a2, unsigned a3,
    unsigned b0, unsigned b1)
{
    asm volatile(
        "mma.sync.aligned.m16n8k16.row.col.f32.f16.f16.f32 "
        "{%0,%1,%2,%3}, {%4,%5,%6,%7}, {%8,%9}, {%0,%1,%2,%3};"
        : "+f"(d0), "+f"(d1), "+f"(d2), "+f"(d3)
        : "r"(a0), "r"(a1), "r"(a2), "r"(a3), "r"(b0), "r"(b1));
}

// pair slot within a 16-element (8-pair) chunk: pairs (gc, gc+4) adjacent
__device__ __forceinline__ int pslot(int w) { return ((w & 3) << 1) + (w >> 2); }

// ---------------------------------------------------------------------------
// tf32 NT GEMM. mode 0: fp32 [M,512]+bias. mode 1/2/3: fp16 packed Q/K/V.
// ---------------------------------------------------------------------------
__global__ __launch_bounds__(256, 2)
void gemm_tf32_kernel(const float* __restrict__ A, const float* __restrict__ W,
                      const float* __restrict__ bias, float* __restrict__ C,
                      __half* __restrict__ Ch, int mode)
{
    __shared__ float As[128][36];
    __shared__ float Bs[64][36];

    const int bm = blockIdx.x * 128;
    const int bn = blockIdx.y * 64;
    const int tid = threadIdx.x;
    const int lane = tid & 31;
    const int warp = tid >> 5;
    const int gr = lane >> 2;
    const int gc = lane & 3;
    const int wm = (warp >> 1) * 32;
    const int wn = (warp & 1) * 32;

    float c[2][4][4] = {};

    for (int k0 = 0; k0 < 512; k0 += 32) {
        #pragma unroll
        for (int i = 0; i < 4; i++) {
            int idx = tid + i * 256;
            int r = idx >> 3, c4 = (idx & 7) * 4;
            float4 v = *(const float4*)(A + (size_t)(bm + r) * 512 + k0 + c4);
            float4 o;
            o.x = __uint_as_float(f2tf(v.x)); o.y = __uint_as_float(f2tf(v.y));
            o.z = __uint_as_float(f2tf(v.z)); o.w = __uint_as_float(f2tf(v.w));
            *(float4*)&As[r][c4] = o;
        }
        #pragma unroll
        for (int i = 0; i < 2; i++) {
            int idx = tid + i * 256;
            int r = idx >> 3, c4 = (idx & 7) * 4;
            float4 v = *(const float4*)(W + (size_t)(bn + r) * 512 + k0 + c4);
            float4 o;
            o.x = __uint_as_float(f2tf(v.x)); o.y = __uint_as_float(f2tf(v.y));
            o.z = __uint_as_float(f2tf(v.z)); o.w = __uint_as_float(f2tf(v.w));
            *(float4*)&Bs[r][c4] = o;
        }
        __syncthreads();

        #pragma unroll
        for (int kk = 0; kk < 4; kk++) {
            const int kc = kk * 8 + gc;
            unsigned a[2][4], b[4][2];
            #pragma unroll
            for (int mt = 0; mt < 2; mt++) {
                int r = wm + mt * 16 + gr;
                a[mt][0] = __float_as_uint(As[r][kc]);
                a[mt][1] = __float_as_uint(As[r + 8][kc]);
                a[mt][2] = __float_as_uint(As[r][kc + 4]);
                a[mt][3] = __float_as_uint(As[r + 8][kc + 4]);
            }
            #pragma unroll
            for (int nt = 0; nt < 4; nt++) {
                int r = wn + nt * 8 + gr;
                b[nt][0] = __float_as_uint(Bs[r][kc]);
                b[nt][1] = __float_as_uint(Bs[r][kc + 4]);
            }
            #pragma unroll
            for (int mt = 0; mt < 2; mt++)
                #pragma unroll
                for (int nt = 0; nt < 4; nt++)
                    mma_tf32(c[mt][nt][0], c[mt][nt][1], c[mt][nt][2], c[mt][nt][3],
                             a[mt][0], a[mt][1], a[mt][2], a[mt][3],
                             b[nt][0], b[nt][1]);
        }
        __syncthreads();
    }

    const float qs = 0.125f * 1.4426950408889634f;

    #pragma unroll
    for (int mt = 0; mt < 2; mt++) {
        #pragma unroll
        for (int nt = 0; nt < 4; nt++) {
            const int r0 = bm + wm + mt * 16 + gr;
            const int e0 = bn + wn + nt * 8 + 2 * gc;
            float v0 = c[mt][nt][0], v1 = c[mt][nt][1];
            float v2 = c[mt][nt][2], v3 = c[mt][nt][3];
            if (mode == 0) {
                const float b0 = bias[e0], b1 = bias[e0 + 1];
                *(float2*)&C[(size_t)r0 * 512 + e0]       = make_float2(v0 + b0, v1 + b1);
                *(float2*)&C[(size_t)(r0 + 8) * 512 + e0] = make_float2(v2 + b0, v3 + b1);
            } else {
                const int hh = e0 >> 6, dd = e0 & 63;
                const int bh0 = (r0 / SEQ) * NHEAD + hh;
                const int ss0 = r0 % SEQ;
                const int bh1 = ((r0 + 8) / SEQ) * NHEAD + hh;
                const int ss1 = (r0 + 8) % SEQ;
                if (mode == 1) {        // Q: plain pairs, scaled
                    ((__half2*)(Ch + ((size_t)bh0 * SEQ + ss0) * 64))[dd >> 1] =
                        __floats2half2_rn(v0 * qs, v1 * qs);
                    ((__half2*)(Ch + ((size_t)bh1 * SEQ + ss1) * 64))[dd >> 1] =
                        __floats2half2_rn(v2 * qs, v3 * qs);
                } else if (mode == 2) { // K: pair-packed + XOR(s&3) on chunk
                    const int q = dd >> 1, ck = q >> 3, sl = pslot(q & 7);
                    ((__half2*)(Ch + ((size_t)bh0 * SEQ + ss0) * 64))
                        [8 * (ck ^ (ss0 & 3)) + sl] = __floats2half2_rn(v0, v1);
                    ((__half2*)(Ch + ((size_t)bh1 * SEQ + ss1) * 64))
                        [8 * (ck ^ (ss1 & 3)) + sl] = __floats2half2_rn(v2, v3);
                } else {                // V: transposed, per-64-tile pair-packed
                    #pragma unroll
                    for (int u = 0; u < 4; u++) {
                        const int d  = dd + (u & 1);          // FIX: within-head index
                        const int bh = (u < 2) ? bh0 : bh1;
                        const int s  = (u < 2) ? ss0 : ss1;
                        const float v = (u == 0) ? v0 : (u == 1) ? v1
                                     : (u == 2) ? v2 : v3;
                        const int st = s & 63, q = st >> 1;
                        const int ck = q >> 3, sl = pslot(q & 7);
                        const int sp = (s & ~63) + 2 * (8 * (ck ^ (d & 3)) + sl) + (s & 1);
                        Ch[((size_t)bh * 64 + d) * SEQ + sp] = __float2half_rn(v);
                    }
                }
            }
        }
    }
}

// ---------------------------------------------------------------------------
// Flash attention, fp16 MMA (m16n8k16, fp32 accum). 128 threads = 4 warps x
// 32 q-rows. 64-key tiles. PV uses the S-accum == A-frag register identity:
// ZERO transpose shuffles. K/V B-frags are conflict-free LDS.64 from the
// XOR-swizzled pair layout written by the projection GEMMs.
// ---------------------------------------------------------------------------
__global__ __launch_bounds__(128, 2)
void attn_tc_kernel(const __half* __restrict__ Q, const __half* __restrict__ Km,
                    const __half* __restrict__ V, float* __restrict__ O)
{
    __shared__ unsigned Ksh[64 * 32];          // 8 KB, 32 pairs/row
    __shared__ unsigned Vsh[64 * 32];          // 8 KB
    __shared__ uint4 Qs[4 * 2 * 4 * 32];       // 16 KB: [warp][mb][chunk][lane]

    const int bh = blockIdx.y;
    const int NT = SEQ / 128;
    const int xt = blockIdx.x;
    const int qtile = (xt & 1) ? (NT - 1 - (xt >> 1)) : (xt >> 1);
    const int qb = qtile * 128;

    const int tid = threadIdx.x;
    const int lane = tid & 31;
    const int warp = tid >> 5;
    const int gr = lane >> 2;
    const int gc = lane & 3;
    const int qr[2] = { qb + warp * 32 + gr, qb + warp * 32 + 16 + gr };

    const __half* Qb = Q  + (size_t)bh * SEQ * HDIM;
    const __half* Kb = Km + (size_t)bh * SEQ * HDIM;
    const __half* Vb = V  + (size_t)bh * HDIM * SEQ;

    // prologue: spill this lane's Q A-fragments to private smem slots
    {
        const unsigned* Qp = (const unsigned*)Qb;
        #pragma unroll
        for (int mb = 0; mb < 2; mb++)
            #pragma unroll
            for (int ck = 0; ck < 4; ck++) {
                uint4 f;
                f.x = Qp[(size_t)qr[mb] * 32 + 8 * ck + gc];
                f.y = Qp[(size_t)(qr[mb] + 8) * 32 + 8 * ck + gc];
                f.z = Qp[(size_t)qr[mb] * 32 + 8 * ck + 4 + gc];
                f.w = Qp[(size_t)(qr[mb] + 8) * 32 + 8 * ck + 4 + gc];
                Qs[((warp * 2 + mb) * 4 + ck) * 32 + lane] = f;
            }
    }

    float o[2][8][4];
    #pragma unroll
    for (int mb = 0; mb < 2; mb++)
        #pragma unroll
        for (int dt = 0; dt < 8; dt++)
            #pragma unroll
            for (int j = 0; j < 4; j++) o[mb][dt][j] = 0.f;
    float mM[2][2] = {{-1e30f, -1e30f}, {-1e30f, -1e30f}};
    float lL[2][2] = {{0.f, 0.f}, {0.f, 0.f}};

    const int ntiles = qb / 64 + 2;
    const int rowxor = (gr & 3);

    for (int kt = 0; kt < ntiles; kt++) {
        // ---- stage K/V tiles (8 KB each, straight uint4 copies) ----
        {
            const uint4* Kg = (const uint4*)(Kb + (size_t)kt * 64 * 64);
            #pragma unroll
            for (int i = 0; i < 4; i++) {
                const int idx = tid + i * 128;
                const int r = idx >> 3, f4 = idx & 7;
                ((uint4*)Ksh)[idx] = Kg[idx];
                ((uint4*)Vsh)[idx] =
                    *(const uint4*)(Vb + (size_t)r * SEQ + kt * 64 + f4 * 8);
            }
        }
        __syncthreads();

        // ---- S = Q K^T (fp16 MMA, k16 over d) ----
        float s[2][8][4];
        #pragma unroll
        for (int mb = 0; mb < 2; mb++)
            #pragma unroll
            for (int nt = 0; nt < 8; nt++)
                #pragma unroll
                for (int j = 0; j < 4; j++) s[mb][nt][j] = 0.f;

        #pragma unroll
        for (int ck = 0; ck < 4; ck++) {
            uint4 qa[2];
            qa[0] = Qs[((warp * 2 + 0) * 4 + ck) * 32 + lane];
            qa[1] = Qs[((warp * 2 + 1) * 4 + ck) * 32 + lane];
            const int cb = 8 * (ck ^ rowxor) + 2 * gc;
            #pragma unroll
            for (int nt = 0; nt < 8; nt++) {
                uint2 kb = *(const uint2*)&Ksh[(nt * 8 + gr) * 32 + cb];
                mma_f16(s[0][nt][0], s[0][nt][1], s[0][nt][2], s[0][nt][3],
                        qa[0].x, qa[0].y, qa[0].z, qa[0].w, kb.x, kb.y);
                mma_f16(s[1][nt][0], s[1][nt][1], s[1][nt][2], s[1][nt][3],
                        qa[1].x, qa[1].y, qa[1].z, qa[1].w, kb.x, kb.y);
            }
        }

        // ---- causal mask ----
        if (kt >= ntiles - 2) {
            #pragma unroll
            for (int mb = 0; mb < 2; mb++)
                #pragma unroll
                for (int nt = 0; nt < 8; nt++) {
                    const int col = kt * 64 + nt * 8 + 2 * gc;
                    if (col > qr[mb])          s[mb][nt][0] = -1e30f;
                    if (col + 1 > qr[mb])      s[mb][nt][1] = -1e30f;
                    if (col > qr[mb] + 8)      s[mb][nt][2] = -1e30f;
                    if (col + 1 > qr[mb] + 8)  s[mb][nt][3] = -1e30f;
                }
        }

        // ---- online softmax (base-2) + pack P to fp16 ----
        unsigned pl[2][8], ph[2][8];
        #pragma unroll
        for (int mb = 0; mb < 2; mb++) {
            float tm0 = -1e30f, tm1 = -1e30f;
            #pragma unroll
            for (int nt = 0; nt < 8; nt++) {
                tm0 = fmaxf(tm0, fmaxf(s[mb][nt][0], s[mb][nt][1]));
                tm1 = fmaxf(tm1, fmaxf(s[mb][nt][2], s[mb][nt][3]));
            }
            tm0 = fmaxf(tm0, __shfl_xor_sync(FULLM, tm0, 1, 4));
            tm0 = fmaxf(tm0, __shfl_xor_sync(FULLM, tm0, 2, 4));
            tm1 = fmaxf(tm1, __shfl_xor_sync(FULLM, tm1, 1, 4));
            tm1 = fmaxf(tm1, __shfl_xor_sync(FULLM, tm1, 2, 4));

            const float nm0 = fmaxf(mM[mb][0], tm0);
            const float nm1 = fmaxf(mM[mb][1], tm1);
            const float sc0 = ex2(mM[mb][0] - nm0);
            const float sc1 = ex2(mM[mb][1] - nm1);

            float r0 = 0.f, r1 = 0.f;
            #pragma unroll
            for (int nt = 0; nt < 8; nt++) {
                float e0 = ex2(s[mb][nt][0] - nm0);
                float e1 = ex2(s[mb][nt][1] - nm0);
                float e2 = ex2(s[mb][nt][2] - nm1);
                float e3 = ex2(s[mb][nt][3] - nm1);
                r0 += e0 + e1;
                r1 += e2 + e3;
                pl[mb][nt] = packh2(e0, e1);
                ph[mb][nt] = packh2(e2, e3);
            }
            r0 += __shfl_xor_sync(FULLM, r0, 1, 4);
            r0 += __shfl_xor_sync(FULLM, r0, 2, 4);
            r1 += __shfl_xor_sync(FULLM, r1, 1, 4);
            r1 += __shfl_xor_sync(FULLM, r1, 2, 4);
            lL[mb][0] = lL[mb][0] * sc0 + r0;
            lL[mb][1] = lL[mb][1] * sc1 + r1;

            #pragma unroll
            for (int dt = 0; dt < 8; dt++) {
                o[mb][dt][0] *= sc0; o[mb][dt][1] *= sc0;
                o[mb][dt][2] *= sc1; o[mb][dt][3] *= sc1;
            }
            mM[mb][0] = nm0; mM[mb][1] = nm1;
        }

        // ---- O += P V (A-frags straight from S accum; zero shuffles) ----
        #pragma unroll
        for (int ck = 0; ck < 4; ck++) {
            const int cb = 8 * (ck ^ rowxor) + 2 * gc;
            #pragma unroll
            for (int dt = 0; dt < 8; dt++) {
                uint2 vb = *(const uint2*)&Vsh[(dt * 8 + gr) * 32 + cb];
                mma_f16(o[0][dt][0], o[0][dt][1], o[0][dt][2], o[0][dt][3],
                        pl[0][2 * ck], ph[0][2 * ck],
                        pl[0][2 * ck + 1], ph[0][2 * ck + 1], vb.x, vb.y);
                mma_f16(o[1][dt][0], o[1][dt][1], o[1][dt][2], o[1][dt][3],
                        pl[1][2 * ck], ph[1][2 * ck],
                        pl[1][2 * ck + 1], ph[1][2 * ck + 1], vb.x, vb.y);
            }
        }

        __syncthreads();
    }

    // ---- epilogue: normalize, store to [B, S, H*DH] ----
    const int b = bh >> 3, h = bh & 7;
    #pragma unroll
    for (int mb = 0; mb < 2; mb++) {
        const float inv0 = 1.f / lL[mb][0];
        const float inv1 = 1.f / lL[mb][1];
        #pragma unroll
        for (int dt = 0; dt < 8; dt++) {
            const int col = dt * 8 + 2 * gc;
            *(float2*)&O[(((size_t)b * SEQ + qr[mb]) * NHEAD + h) * HDIM + col] =
                make_float2(o[mb][dt][0] * inv0, o[mb][dt][1] * inv0);
            *(float2*)&O[(((size_t)b * SEQ + qr[mb] + 8) * NHEAD + h) * HDIM + col] =
                make_float2(o[mb][dt][2] * inv1, o[mb][dt][3] * inv1);
        }
    }
}

// ---------------------------------------------------------------------------
extern "C" void kernel_launch(void* const* d_in, const int* in_sizes, int n_in,
                              void* d_out, int out_size)
{
    const float* x  = (const float*)d_in[0];
    const float* Wq = (const float*)d_in[1];
    const float* Wk = (const float*)d_in[2];
    const float* Wv = (const float*)d_in[3];
    const float* Wp = (const float*)d_in[4];
    const float* bp = (const float*)d_in[5];
    float* out = (float*)d_out;

    __half *qp, *kp, *vp;
    float *ap;
    cudaGetSymbolAddress((void**)&qp, g_qh);
    cudaGetSymbolAddress((void**)&kp, g_kh);
    cudaGetSymbolAddress((void**)&vp, g_vh);
    cudaGetSymbolAddress((void**)&ap, g_attn);

    dim3 gg(BATCH * SEQ / 128, DMODEL / 64);   // (64, 8)
    gemm_tf32_kernel<<<gg, 256>>>(x, Wq, nullptr, nullptr, qp, 1);
    gemm_tf32_kernel<<<gg, 256>>>(x, Wk, nullptr, nullptr, kp, 2);
    gemm_tf32_kernel<<<gg, 256>>>(x, Wv, nullptr, nullptr, vp, 3);

    dim3 ga(SEQ / 128, BATCH * NHEAD);          // (32, 16)
    attn_tc_kernel<<<ga, 128>>>(qp, kp, vp, ap);

    gemm_tf32_kernel<<<gg, 256>>>(ap, Wp, bp, out, nullptr, 0);
}